// round 2
// baseline (speedup 1.0000x reference)
#include <cuda_runtime.h>
#include <math.h>

#define AA     15
#define HW     16384
#define NUM    245760
#define NB     16
#define NROW   32
#define PRE    2000
#define POST   1000
#define CANDN  4096
#define MASKW  32
#define NEGV   (-1000000000.0f)
#define CLIPV  4.135166556742356f
#define IMGMAX 1023.0f
#define NEEDK  2048u   /* select top-2048 by logit; margin for sigmoid ties */

__device__ unsigned int       g_hist[NROW * 4096];
__device__ unsigned int       g_state[NROW * 2];       // [0]=prefix/threshold, [1]=need
__device__ unsigned int       g_cand_cnt[NROW];
__device__ unsigned long long g_cand[NROW * CANDN];
__device__ int                g_topk_idx[NROW * 2048];
__device__ float              g_topk_score[NROW * 2048];
__device__ float4             g_props[NROW * PRE];
__device__ float              g_area[NROW * PRE];
__device__ unsigned char      g_valid[NROW * PRE];
__device__ unsigned long long g_mask[(size_t)NROW * PRE * MASKW];
__device__ int                g_keep[NROW * PRE];

// Monotone bit transform: order of mono(x) == order of float x
__device__ __forceinline__ unsigned int mono(float x) {
    unsigned int b = __float_as_uint(x);
    return b ^ ((b & 0x80000000u) ? 0xFFFFFFFFu : 0x80000000u);
}

// XLA LogisticExpander: 1 / (1 + exp(-x)), exp = libdevice __nv_expf
__device__ __forceinline__ float ref_sigmoid(float x) {
    float e = expf(-x);
    return __fdiv_rn(1.0f, __fadd_rn(1.0f, e));
}

// ---------------- histogram passes (radix select on logit bits) ----------------
__global__ void k_hist1(const float* __restrict__ objL, const float* __restrict__ objR) {
    int row = blockIdx.y;
    const float* obj = ((row >> 4) ? objR : objL) + (size_t)(row & 15) * NUM;
    __shared__ unsigned int sh[4096];
    for (int i = threadIdx.x; i < 4096; i += blockDim.x) sh[i] = 0u;
    __syncthreads();
    int base = blockIdx.x * 4096;
    for (int k = threadIdx.x; k < 4096; k += blockDim.x) {
        unsigned int u = mono(obj[base + k]);
        atomicAdd(&sh[u >> 20], 1u);
    }
    __syncthreads();
    for (int i = threadIdx.x; i < 4096; i += blockDim.x)
        if (sh[i]) atomicAdd(&g_hist[row * 4096 + i], sh[i]);
}

__global__ void k_hist2(const float* __restrict__ objL, const float* __restrict__ objR) {
    int row = blockIdx.y;
    const float* obj = ((row >> 4) ? objR : objL) + (size_t)(row & 15) * NUM;
    unsigned int pref = g_state[row * 2 + 0];
    __shared__ unsigned int sh[4096];
    for (int i = threadIdx.x; i < 4096; i += blockDim.x) sh[i] = 0u;
    __syncthreads();
    int base = blockIdx.x * 4096;
    for (int k = threadIdx.x; k < 4096; k += blockDim.x) {
        unsigned int u = mono(obj[base + k]);
        if ((u >> 20) == pref) atomicAdd(&sh[(u >> 8) & 0xFFFu], 1u);
    }
    __syncthreads();
    for (int i = threadIdx.x; i < 4096; i += blockDim.x)
        if (sh[i]) atomicAdd(&g_hist[row * 4096 + i], sh[i]);
}

__global__ void k_hist3(const float* __restrict__ objL, const float* __restrict__ objR) {
    int row = blockIdx.y;
    const float* obj = ((row >> 4) ? objR : objL) + (size_t)(row & 15) * NUM;
    unsigned int pref = g_state[row * 2 + 0];   // top-24 bits
    __shared__ unsigned int sh[256];
    for (int i = threadIdx.x; i < 256; i += blockDim.x) sh[i] = 0u;
    __syncthreads();
    int base = blockIdx.x * 4096;
    for (int k = threadIdx.x; k < 4096; k += blockDim.x) {
        unsigned int u = mono(obj[base + k]);
        if ((u >> 8) == pref) atomicAdd(&sh[u & 0xFFu], 1u);
    }
    __syncthreads();
    for (int i = threadIdx.x; i < 256; i += blockDim.x)
        if (sh[i]) atomicAdd(&g_hist[row * 4096 + i], sh[i]);
}

// pass 0: top 12 bits, pass 1: mid 12 bits, pass 2: low 8 bits
__global__ void k_resolve(int pass) {
    int row = blockIdx.x;
    if (threadIdx.x == 0) {
        unsigned int need   = (pass == 0) ? NEEDK : g_state[row * 2 + 1];
        unsigned int prefix = (pass == 0) ? 0u : g_state[row * 2 + 0];
        int bins  = (pass == 2) ? 256 : 4096;
        int shift = (pass == 2) ? 8 : 12;
        unsigned int* h = &g_hist[row * 4096];
        unsigned int cum = 0;
        for (int i = bins - 1; i >= 0; --i) {
            unsigned int c = h[i];
            if (cum + c >= need) {
                prefix = (prefix << shift) | (unsigned)i;
                need   = need - cum;
                break;
            }
            cum += c;
        }
        g_state[row * 2 + 0] = prefix;
        g_state[row * 2 + 1] = need;
        if (pass == 2) g_cand_cnt[row] = 0u;   // reset for gather
    }
    __syncthreads();
    for (int i = threadIdx.x; i < 4096; i += blockDim.x) g_hist[row * 4096 + i] = 0u;
}

// gather candidates with logit-bits >= threshold; key = (sigmoid_bits, ~ref_idx)
__global__ void k_gather(const float* __restrict__ objL, const float* __restrict__ objR) {
    int row = blockIdx.y;
    const float* obj = ((row >> 4) ? objR : objL) + (size_t)(row & 15) * NUM;
    unsigned int T = g_state[row * 2 + 0];
    int base = blockIdx.x * 4096;
    for (int k = threadIdx.x; k < 4096; k += blockDim.x) {
        int j = base + k;
        float x = obj[j];
        if (mono(x) >= T) {
            unsigned int pos = atomicAdd(&g_cand_cnt[row], 1u);
            if (pos < CANDN) {
                unsigned int sb = __float_as_uint(ref_sigmoid(x));  // positive -> monotone bits
                int a = j >> 14;                 // j = a*HW + p
                int p = j & (HW - 1);
                unsigned int i = (unsigned)(p * AA + a);
                g_cand[row * CANDN + pos] =
                    ((unsigned long long)sb << 32) | (unsigned long long)(~i);
            }
        }
    }
}

// per-row bitonic sort, descending by (sigmoid bits, ~idx)
__global__ void k_sort() {
    __shared__ unsigned long long s[CANDN];
    int row = blockIdx.x;
    unsigned int cnt = g_cand_cnt[row];
    if (cnt > CANDN) cnt = CANDN;
    for (int i = threadIdx.x; i < CANDN; i += blockDim.x)
        s[i] = (i < (int)cnt) ? g_cand[row * CANDN + i] : 0ULL;
    __syncthreads();
    for (int k = 2; k <= CANDN; k <<= 1) {
        for (int j = k >> 1; j > 0; j >>= 1) {
            for (int t = threadIdx.x; t < CANDN / 2; t += blockDim.x) {
                int i   = 2 * t - (t & (j - 1));
                int ixj = i + j;
                bool dir = ((i & k) == 0);
                unsigned long long a = s[i], b = s[ixj];
                if (dir ? (a < b) : (a > b)) { s[i] = b; s[ixj] = a; }
            }
            __syncthreads();
        }
    }
    for (int p = threadIdx.x; p < PRE; p += blockDim.x) {
        unsigned long long key = s[p];
        g_topk_idx[row * 2048 + p]   = (int)(~(unsigned int)key);
        g_topk_score[row * 2048 + p] = __uint_as_float((unsigned int)(key >> 32));
    }
}

__global__ void k_decode(const float* __restrict__ ancL, const float* __restrict__ ancR,
                         const float* __restrict__ brL,  const float* __restrict__ brR) {
    int k = blockIdx.x * blockDim.x + threadIdx.x;
    if (k >= PRE) return;
    int row = blockIdx.y;
    int side = row >> 4, n = row & 15;
    int i = g_topk_idx[row * 2048 + k];
    int a = i % AA;
    int p = i / AA;
    const float* anc = (side ? ancR : ancL) + ((size_t)n * NUM + (size_t)i) * 4;
    float4 ab = *(const float4*)anc;
    const float* br = (side ? brR : brL) + ((size_t)n * AA * 4 + a * 4) * HW + p;
    float dx = br[0];
    float dy = br[HW];
    float dw = fminf(br[2 * HW], CLIPV);
    float dh = fminf(br[3 * HW], CLIPV);
    float wa = __fadd_rn(__fadd_rn(ab.z, -ab.x), 1.0f);
    float ha = __fadd_rn(__fadd_rn(ab.w, -ab.y), 1.0f);
    float cx = __fadd_rn(ab.x, __fmul_rn(0.5f, wa));
    float cy = __fadd_rn(ab.y, __fmul_rn(0.5f, ha));
    float pcx = __fadd_rn(__fmul_rn(dx, wa), cx);
    float pcy = __fadd_rn(__fmul_rn(dy, ha), cy);
    float pw = __fmul_rn(expf(dw), wa);
    float ph = __fmul_rn(expf(dh), ha);
    float hpw = __fmul_rn(0.5f, pw);
    float hph = __fmul_rn(0.5f, ph);
    float x1 = __fadd_rn(pcx, -hpw);
    float y1 = __fadd_rn(pcy, -hph);
    float x2 = __fadd_rn(__fadd_rn(pcx, hpw), -1.0f);
    float y2 = __fadd_rn(__fadd_rn(pcy, hph), -1.0f);
    x1 = fminf(fmaxf(x1, 0.0f), IMGMAX);
    y1 = fminf(fmaxf(y1, 0.0f), IMGMAX);
    x2 = fminf(fmaxf(x2, 0.0f), IMGMAX);
    y2 = fminf(fmaxf(y2, 0.0f), IMGMAX);
    float ws = __fadd_rn(__fadd_rn(x2, -x1), 1.0f);
    float hs = __fadd_rn(__fadd_rn(y2, -y1), 1.0f);
    g_props[row * PRE + k] = make_float4(x1, y1, x2, y2);
    g_area[row * PRE + k]  = __fmul_rn(ws, hs);
    g_valid[row * PRE + k] = (ws >= 4.0f) && (hs >= 4.0f);
}

// IoU bitmask: bit j of word cb of row i set iff gj=cb*64+j > i and IoU > 0.7
__global__ void k_mask() {
    int cb = blockIdx.x, rb = blockIdx.y, row = blockIdx.z;
    int t = threadIdx.x;   // 64
    __shared__ float4 cbox[64];
    __shared__ float  carea[64];
    int cj = cb * 64 + t;
    if (cj < PRE) { cbox[t] = g_props[row * PRE + cj]; carea[t] = g_area[row * PRE + cj]; }
    else          { cbox[t] = make_float4(0.f,0.f,0.f,0.f); carea[t] = 0.f; }
    __syncthreads();
    int ri = rb * 64 + t;
    if (ri >= PRE) return;
    float4 bi = g_props[row * PRE + ri];
    float  ai = g_area[row * PRE + ri];
    unsigned long long bits = 0;
    #pragma unroll 8
    for (int jj = 0; jj < 64; jj++) {
        int gj = cb * 64 + jj;
        if (gj > ri && gj < PRE) {
            float xx1 = fmaxf(bi.x, cbox[jj].x);
            float yy1 = fmaxf(bi.y, cbox[jj].y);
            float xx2 = fminf(bi.z, cbox[jj].z);
            float yy2 = fminf(bi.w, cbox[jj].w);
            float iw = fmaxf(__fadd_rn(__fadd_rn(xx2, -xx1), 1.0f), 0.0f);
            float ih = fmaxf(__fadd_rn(__fadd_rn(yy2, -yy1), 1.0f), 0.0f);
            float inter = __fmul_rn(iw, ih);
            float uni = __fadd_rn(__fadd_rn(ai, carea[jj]), -inter);
            float iou = __fdiv_rn(inter, uni);
            if (iou > 0.7f) bits |= (1ULL << jj);
        }
    }
    g_mask[((size_t)row * PRE + ri) * MASKW + cb] = bits;
}

// sequential greedy NMS scan, 1 warp per row, depth-8 prefetch pipeline
__global__ void k_nms() {
    __shared__ unsigned char sv[PRE];
    int row = blockIdx.x, t = threadIdx.x;   // 32
    for (int i = t; i < PRE; i += 32) sv[i] = g_valid[row * PRE + i];
    __syncwarp();
    const unsigned long long* m = g_mask + (size_t)row * PRE * MASKW;
    unsigned long long pipe[8];
    #pragma unroll
    for (int p = 0; p < 8; p++) pipe[p] = m[(size_t)p * MASKW + t];
    unsigned long long rem = 0;
    for (int i = 0; i < PRE; i++) {
        int slot = i & 7;
        unsigned long long w = __shfl_sync(0xffffffffu, rem, i >> 6);
        int kp = sv[i] && !((w >> (i & 63)) & 1ULL);
        if (kp) rem |= pipe[slot];
        if (t == 0) g_keep[row * PRE + i] = kp;
        int nx = i + 8;
        pipe[slot] = (nx < PRE) ? m[(size_t)nx * MASKW + t] : 0ULL;
    }
}

// stable partition: kept first (descending-score order), then fillers (ascending idx)
__global__ void k_final(float* __restrict__ out) {
    __shared__ int sa[2048], sb[2048];
    int row = blockIdx.x;
    for (int i = threadIdx.x; i < 2048; i += blockDim.x)
        sa[i] = (i < PRE) ? g_keep[row * PRE + i] : 0;
    __syncthreads();
    int* src = sa; int* dst = sb;
    for (int d = 1; d < 2048; d <<= 1) {
        for (int i = threadIdx.x; i < 2048; i += blockDim.x)
            dst[i] = src[i] + ((i >= d) ? src[i - d] : 0);
        __syncthreads();
        int* tmp = src; src = dst; dst = tmp;
    }
    int total = src[PRE - 1];
    for (int p = threadIdx.x; p < PRE; p += blockDim.x) {
        int f    = g_keep[row * PRE + p];
        int incl = src[p];
        int excl = incl - f;
        int pos  = f ? excl : (total + p - excl);
        if (pos < POST) {
            float4 b = g_props[row * PRE + p];
            float sc = f ? g_topk_score[row * 2048 + p] : NEGV;
            float* o = out + ((size_t)row * POST + pos) * 5;
            o[0] = b.x; o[1] = b.y; o[2] = b.z; o[3] = b.w; o[4] = sc;
        }
    }
}

extern "C" void kernel_launch(void* const* d_in, const int* in_sizes, int n_in,
                              void* d_out, int out_size) {
    const float* ancL = (const float*)d_in[0];
    const float* ancR = (const float*)d_in[1];
    const float* objL = (const float*)d_in[2];
    const float* objR = (const float*)d_in[3];
    const float* brL  = (const float*)d_in[4];
    const float* brR  = (const float*)d_in[5];
    float* out = (float*)d_out;

    dim3 gHist(60, NROW);
    k_hist1<<<gHist, 256>>>(objL, objR);
    k_resolve<<<NROW, 256>>>(0);
    k_hist2<<<gHist, 256>>>(objL, objR);
    k_resolve<<<NROW, 256>>>(1);
    k_hist3<<<gHist, 256>>>(objL, objR);
    k_resolve<<<NROW, 256>>>(2);
    k_gather<<<gHist, 256>>>(objL, objR);
    k_sort<<<NROW, 512>>>();
    dim3 gDec((PRE + 255) / 256, NROW);
    k_decode<<<gDec, 256>>>(ancL, ancR, brL, brR);
    dim3 gMask(MASKW, (PRE + 63) / 64, NROW);
    k_mask<<<gMask, 64>>>();
    k_nms<<<NROW, 32>>>();
    k_final<<<NROW, 256>>>(out);
}

// round 3
// speedup vs baseline: 2.9402x; 2.9402x over previous
#include <cuda_runtime.h>
#include <math.h>

#define AA     15
#define HW     16384
#define NUM    245760
#define NROW   32
#define PRE    2000
#define POST   1000
#define CANDN  4096
#define MASKW  32
#define NEGV   (-1000000000.0f)
#define CLIPV  4.135166556742356f
#define IMGMAX 1023.0f
#define NEEDK  2048u

__device__ unsigned int       g_hist[NROW * 4096];
__device__ unsigned int       g_state[NROW * 2];
__device__ unsigned int       g_cand_cnt[NROW];
__device__ unsigned long long g_cand[NROW * CANDN];
__device__ int                g_topk_idx[NROW * 2048];
__device__ float              g_topk_score[NROW * 2048];
__device__ float4             g_props[NROW * PRE];
__device__ float              g_area[NROW * PRE];
__device__ unsigned char      g_valid[NROW * PRE];
__device__ unsigned long long g_mask[(size_t)NROW * PRE * MASKW];
__device__ int                g_keep[NROW * PRE];

__device__ __forceinline__ unsigned int mono(float x) {
    unsigned int b = __float_as_uint(x);
    return b ^ ((b & 0x80000000u) ? 0xFFFFFFFFu : 0x80000000u);
}
__device__ __forceinline__ float ref_sigmoid(float x) {
    float e = expf(-x);
    return __fdiv_rn(1.0f, __fadd_rn(1.0f, e));
}

// ---------- histogram passes (radix select on logit bits) ----------
__global__ void k_hist1(const float* __restrict__ objL, const float* __restrict__ objR) {
    int row = blockIdx.y;
    const float* obj = ((row >> 4) ? objR : objL) + (size_t)(row & 15) * NUM;
    __shared__ unsigned int sh[4096];
    for (int i = threadIdx.x; i < 4096; i += blockDim.x) sh[i] = 0u;
    __syncthreads();
    int base = blockIdx.x * 4096;
    for (int k = threadIdx.x; k < 4096; k += blockDim.x) {
        unsigned int u = mono(obj[base + k]);
        atomicAdd(&sh[u >> 20], 1u);
    }
    __syncthreads();
    for (int i = threadIdx.x; i < 4096; i += blockDim.x)
        if (sh[i]) atomicAdd(&g_hist[row * 4096 + i], sh[i]);
}

__global__ void k_hist2(const float* __restrict__ objL, const float* __restrict__ objR) {
    int row = blockIdx.y;
    const float* obj = ((row >> 4) ? objR : objL) + (size_t)(row & 15) * NUM;
    unsigned int pref = g_state[row * 2 + 0];
    __shared__ unsigned int sh[4096];
    for (int i = threadIdx.x; i < 4096; i += blockDim.x) sh[i] = 0u;
    __syncthreads();
    int base = blockIdx.x * 4096;
    for (int k = threadIdx.x; k < 4096; k += blockDim.x) {
        unsigned int u = mono(obj[base + k]);
        if ((u >> 20) == pref) atomicAdd(&sh[(u >> 8) & 0xFFFu], 1u);
    }
    __syncthreads();
    for (int i = threadIdx.x; i < 4096; i += blockDim.x)
        if (sh[i]) atomicAdd(&g_hist[row * 4096 + i], sh[i]);
}

// Parallel bin selection: suffix scan over 4096 bins with 256 threads.
// pass 0: top-12 bits -> prefix12; pass 1: next-12 bits -> prefix24 (+reset cand_cnt)
__global__ void k_resolve(int pass) {
    int row = blockIdx.x;
    int t = threadIdx.x;     // 256 threads
    __shared__ unsigned int ssum[256];
    unsigned int need   = (pass == 0) ? NEEDK : g_state[row * 2 + 1];
    unsigned int prefix = (pass == 0) ? 0u    : g_state[row * 2 + 0];
    unsigned int hl[16];
    unsigned int s = 0;
    #pragma unroll
    for (int k = 0; k < 16; k++) { hl[k] = g_hist[row * 4096 + t * 16 + k]; s += hl[k]; }
    ssum[t] = s;
    __syncthreads();
    // inclusive suffix scan: ssum[t] = sum_{j>=t}
    #pragma unroll
    for (int off = 1; off < 256; off <<= 1) {
        unsigned int v = (t + off < 256) ? ssum[t + off] : 0u;
        __syncthreads();
        ssum[t] += v;
        __syncthreads();
    }
    unsigned int incl  = ssum[t];
    unsigned int above = incl - s;
    if (above < need && need <= incl) {
        unsigned int cum = above;
        #pragma unroll
        for (int k = 15; k >= 0; --k) {
            unsigned int c = hl[k];
            if (cum + c >= need) {
                g_state[row * 2 + 0] = (prefix << 12) | (unsigned)(t * 16 + k);
                g_state[row * 2 + 1] = need - cum;
                break;
            }
            cum += c;
        }
        if (pass == 1) g_cand_cnt[row] = 0u;
    }
    __syncthreads();
    for (int i = t; i < 4096; i += 256) g_hist[row * 4096 + i] = 0u;
}

// gather all elems with top-24 mono bits >= prefix24 (superset of top-2048; bin at
// threshold holds O(1) elems for this data, cap 4096 gives huge slack)
__global__ void k_gather(const float* __restrict__ objL, const float* __restrict__ objR) {
    int row = blockIdx.y;
    const float* obj = ((row >> 4) ? objR : objL) + (size_t)(row & 15) * NUM;
    unsigned int T = g_state[row * 2 + 0] << 8;
    int base = blockIdx.x * 4096;
    for (int k = threadIdx.x; k < 4096; k += blockDim.x) {
        int j = base + k;
        float x = obj[j];
        if (mono(x) >= T) {
            unsigned int pos = atomicAdd(&g_cand_cnt[row], 1u);
            if (pos < CANDN) {
                unsigned int sb = __float_as_uint(ref_sigmoid(x));
                int a = j >> 14;
                int p = j & (HW - 1);
                unsigned int i = (unsigned)(p * AA + a);
                g_cand[row * CANDN + pos] =
                    ((unsigned long long)sb << 32) | (unsigned long long)(~i);
            }
        }
    }
}

// per-row bitonic sort, descending by (sigmoid bits, ~idx)
__global__ void k_sort() {
    __shared__ unsigned long long s[CANDN];
    int row = blockIdx.x;
    unsigned int cnt = g_cand_cnt[row];
    if (cnt > CANDN) cnt = CANDN;
    for (int i = threadIdx.x; i < CANDN; i += blockDim.x)
        s[i] = (i < (int)cnt) ? g_cand[row * CANDN + i] : 0ULL;
    __syncthreads();
    for (int k = 2; k <= CANDN; k <<= 1) {
        for (int j = k >> 1; j > 0; j >>= 1) {
            for (int t = threadIdx.x; t < CANDN / 2; t += blockDim.x) {
                int i   = 2 * t - (t & (j - 1));
                int ixj = i + j;
                bool dir = ((i & k) == 0);
                unsigned long long a = s[i], b = s[ixj];
                if (dir ? (a < b) : (a > b)) { s[i] = b; s[ixj] = a; }
            }
            __syncthreads();
        }
    }
    for (int p = threadIdx.x; p < PRE; p += blockDim.x) {
        unsigned long long key = s[p];
        g_topk_idx[row * 2048 + p]   = (int)(~(unsigned int)key);
        g_topk_score[row * 2048 + p] = __uint_as_float((unsigned int)(key >> 32));
    }
}

__global__ void k_decode(const float* __restrict__ ancL, const float* __restrict__ ancR,
                         const float* __restrict__ brL,  const float* __restrict__ brR) {
    int k = blockIdx.x * blockDim.x + threadIdx.x;
    if (k >= PRE) return;
    int row = blockIdx.y;
    int side = row >> 4, n = row & 15;
    int i = g_topk_idx[row * 2048 + k];
    int a = i % AA;
    int p = i / AA;
    const float* anc = (side ? ancR : ancL) + ((size_t)n * NUM + (size_t)i) * 4;
    float4 ab = *(const float4*)anc;
    const float* br = (side ? brR : brL) + ((size_t)n * AA * 4 + a * 4) * HW + p;
    float dx = br[0];
    float dy = br[HW];
    float dw = fminf(br[2 * HW], CLIPV);
    float dh = fminf(br[3 * HW], CLIPV);
    float wa = __fadd_rn(__fadd_rn(ab.z, -ab.x), 1.0f);
    float ha = __fadd_rn(__fadd_rn(ab.w, -ab.y), 1.0f);
    float cx = __fadd_rn(ab.x, __fmul_rn(0.5f, wa));
    float cy = __fadd_rn(ab.y, __fmul_rn(0.5f, ha));
    float pcx = __fadd_rn(__fmul_rn(dx, wa), cx);
    float pcy = __fadd_rn(__fmul_rn(dy, ha), cy);
    float pw = __fmul_rn(expf(dw), wa);
    float ph = __fmul_rn(expf(dh), ha);
    float hpw = __fmul_rn(0.5f, pw);
    float hph = __fmul_rn(0.5f, ph);
    float x1 = __fadd_rn(pcx, -hpw);
    float y1 = __fadd_rn(pcy, -hph);
    float x2 = __fadd_rn(__fadd_rn(pcx, hpw), -1.0f);
    float y2 = __fadd_rn(__fadd_rn(pcy, hph), -1.0f);
    x1 = fminf(fmaxf(x1, 0.0f), IMGMAX);
    y1 = fminf(fmaxf(y1, 0.0f), IMGMAX);
    x2 = fminf(fmaxf(x2, 0.0f), IMGMAX);
    y2 = fminf(fmaxf(y2, 0.0f), IMGMAX);
    float ws = __fadd_rn(__fadd_rn(x2, -x1), 1.0f);
    float hs = __fadd_rn(__fadd_rn(y2, -y1), 1.0f);
    g_props[row * PRE + k] = make_float4(x1, y1, x2, y2);
    g_area[row * PRE + k]  = __fmul_rn(ws, hs);
    g_valid[row * PRE + k] = (ws >= 4.0f) && (hs >= 4.0f);
}

// IoU bitmask, upper triangle only (lower blocks store zeros, no compute)
__global__ void k_mask() {
    int cb = blockIdx.x, rb = blockIdx.y, row = blockIdx.z;
    int t = threadIdx.x;   // 64
    int ri = rb * 64 + t;
    if (cb < rb) {                           // all gj <= all ri: zero words
        if (ri < PRE) g_mask[((size_t)row * PRE + ri) * MASKW + cb] = 0ULL;
        return;
    }
    __shared__ float4 cbox[64];
    __shared__ float  carea[64];
    int cj = cb * 64 + t;
    if (cj < PRE) { cbox[t] = g_props[row * PRE + cj]; carea[t] = g_area[row * PRE + cj]; }
    else          { cbox[t] = make_float4(0.f,0.f,0.f,0.f); carea[t] = 0.f; }
    __syncthreads();
    if (ri >= PRE) return;
    float4 bi = g_props[row * PRE + ri];
    float  ai = g_area[row * PRE + ri];
    unsigned long long bits = 0;
    #pragma unroll 8
    for (int jj = 0; jj < 64; jj++) {
        int gj = cb * 64 + jj;
        if (gj > ri && gj < PRE) {
            float xx1 = fmaxf(bi.x, cbox[jj].x);
            float yy1 = fmaxf(bi.y, cbox[jj].y);
            float xx2 = fminf(bi.z, cbox[jj].z);
            float yy2 = fminf(bi.w, cbox[jj].w);
            float iw = fmaxf(__fadd_rn(__fadd_rn(xx2, -xx1), 1.0f), 0.0f);
            float ih = fmaxf(__fadd_rn(__fadd_rn(yy2, -yy1), 1.0f), 0.0f);
            float inter = __fmul_rn(iw, ih);
            float uni = __fadd_rn(__fadd_rn(ai, carea[jj]), -inter);
            float iou = __fdiv_rn(inter, uni);
            if (iou > 0.7f) bits |= (1ULL << jj);
        }
    }
    g_mask[((size_t)row * PRE + ri) * MASKW + cb] = bits;
}

// sequential greedy NMS: all lanes maintain the live 64-bit word via broadcast
// loads (off the dependency chain); shfl only at 64-item block boundaries.
__global__ void k_nms() {
    __shared__ unsigned char sv[PRE];
    int row = blockIdx.x, t = threadIdx.x;   // 32
    for (int i = t; i < PRE; i += 32) sv[i] = g_valid[row * PRE + i];
    __syncwarp();
    const unsigned long long* m = g_mask + (size_t)row * PRE * MASKW;
    unsigned long long pm[16], bm[16];
    #pragma unroll
    for (int p = 0; p < 16; p++) {
        pm[p] = m[(size_t)p * MASKW + t];
        bm[p] = m[(size_t)p * MASKW + (p >> 6)];
    }
    unsigned long long rem = 0, cur = 0;
    for (int ii = 0; ii < PRE / 16; ii++) {
        #pragma unroll
        for (int k = 0; k < 16; k++) {
            int i = ii * 16 + k;
            int j = i & 63;
            if (j == 0) cur = __shfl_sync(0xffffffffu, rem, i >> 6);
            unsigned long long mb = bm[k], mp = pm[k];
            int kp = sv[i] && !((cur >> j) & 1ULL);
            unsigned long long msk = (unsigned long long)(-(long long)kp);
            cur |= mb & msk;
            rem |= mp & msk;
            if (t == 0) g_keep[row * PRE + i] = kp;
            int nx = i + 16;
            if (nx < PRE) {
                pm[k] = m[(size_t)nx * MASKW + t];
                bm[k] = m[(size_t)nx * MASKW + (nx >> 6)];
            } else { pm[k] = 0; bm[k] = 0; }
        }
    }
}

// stable partition: kept first (descending score), fillers after (score NEG)
__global__ void k_final(float* __restrict__ out) {
    __shared__ int sa[2048], sb[2048];
    int row = blockIdx.x;
    for (int i = threadIdx.x; i < 2048; i += blockDim.x)
        sa[i] = (i < PRE) ? g_keep[row * PRE + i] : 0;
    __syncthreads();
    int* src = sa; int* dst = sb;
    for (int d = 1; d < 2048; d <<= 1) {
        for (int i = threadIdx.x; i < 2048; i += blockDim.x)
            dst[i] = src[i] + ((i >= d) ? src[i - d] : 0);
        __syncthreads();
        int* tmp = src; src = dst; dst = tmp;
    }
    int total = src[PRE - 1];
    for (int p = threadIdx.x; p < PRE; p += blockDim.x) {
        int f    = g_keep[row * PRE + p];
        int incl = src[p];
        int excl = incl - f;
        int pos  = f ? excl : (total + p - excl);
        if (pos < POST) {
            float4 b = g_props[row * PRE + p];
            float sc = f ? g_topk_score[row * 2048 + p] : NEGV;
            float* o = out + ((size_t)row * POST + pos) * 5;
            o[0] = b.x; o[1] = b.y; o[2] = b.z; o[3] = b.w; o[4] = sc;
        }
    }
}

extern "C" void kernel_launch(void* const* d_in, const int* in_sizes, int n_in,
                              void* d_out, int out_size) {
    const float* ancL = (const float*)d_in[0];
    const float* ancR = (const float*)d_in[1];
    const float* objL = (const float*)d_in[2];
    const float* objR = (const float*)d_in[3];
    const float* brL  = (const float*)d_in[4];
    const float* brR  = (const float*)d_in[5];
    float* out = (float*)d_out;

    dim3 gHist(60, NROW);
    k_hist1<<<gHist, 256>>>(objL, objR);
    k_resolve<<<NROW, 256>>>(0);
    k_hist2<<<gHist, 256>>>(objL, objR);
    k_resolve<<<NROW, 256>>>(1);
    k_gather<<<gHist, 256>>>(objL, objR);
    k_sort<<<NROW, 512>>>();
    dim3 gDec((PRE + 255) / 256, NROW);
    k_decode<<<gDec, 256>>>(ancL, ancR, brL, brR);
    dim3 gMask(MASKW, (PRE + 63) / 64, NROW);
    k_mask<<<gMask, 64>>>();
    k_nms<<<NROW, 32>>>();
    k_final<<<NROW, 256>>>(out);
}